// round 11
// baseline (speedup 1.0000x reference)
#include <cuda_runtime.h>
#include <cuda_fp16.h>
#include <cstdint>

// Router: alpha = softmax(topk_mask(z @ W^T + b))
// z:[8192,4096]f32  W:[64,4096]f32  b:[64]f32  k=2
// K1: split-K(8) GEMM, fp16 2-tier split (z=z1+z2, 64W=w1+w2),
//     mma.sync m16n8k16, 3-stage ring, prefetch-2, STS.128 producers.
// K2: reduce 8 partials, *1/64, +bias, top-k mask, softmax.

namespace {
typedef uint32_t u32;
constexpr int D = 4096;
constexpr int KSPLIT = 8;
constexpr int KH = D / KSPLIT;       // 512
constexpr int BM = 64;
constexpr int BK = 32;
constexpr int NSTG = KH / BK;        // 16
constexpr int NT1 = 256;
constexpr int Kc = 64;
constexpr int NROWS = 8192;

constexpr int ROWB = 80;             // 32 halfs + 8 pad; 16B-aligned rows
constexpr int A1_OFF = 0;            // 64*80 = 5120B per tier
constexpr int A2_OFF = 5120;
constexpr int B1_OFF = 10240;
constexpr int B2_OFF = 15360;
constexpr int STG_B = 20480;
constexpr int SMEM1 = 3 * STG_B;     // 61440 dynamic

__device__ float g_part[KSPLIT * NROWS * Kc];  // 16MB scratch

__device__ __forceinline__ void mma16(float* d, const u32* a, u32 b0, u32 b1) {
    asm volatile(
        "mma.sync.aligned.m16n8k16.row.col.f32.f16.f16.f32 "
        "{%0,%1,%2,%3}, {%4,%5,%6,%7}, {%8,%9}, {%0,%1,%2,%3};"
        : "+f"(d[0]), "+f"(d[1]), "+f"(d[2]), "+f"(d[3])
        : "r"(a[0]), "r"(a[1]), "r"(a[2]), "r"(a[3]), "r"(b0), "r"(b1));
}
__device__ __forceinline__ void ldsm4(u32* r, u32 addr) {
    asm volatile(
        "ldmatrix.sync.aligned.m8n8.x4.shared.b16 {%0,%1,%2,%3}, [%4];"
        : "=r"(r[0]), "=r"(r[1]), "=r"(r[2]), "=r"(r[3]) : "r"(addr));
}
__device__ __forceinline__ u32 smem_u32(const void* p) {
    u32 a;
    asm("{ .reg .u64 t; cvta.to.shared.u64 t, %1; cvt.u32.u64 %0, t; }"
        : "=r"(a) : "l"(p));
    return a;
}
// 2-tier split of 8 floats -> tier1 16B + tier2 16B (one STS.128 each).
__device__ __forceinline__ void split8(float4 a, float4 c, uint4& t1, uint4& t2) {
    __half h0 = __float2half_rn(a.x), h1 = __float2half_rn(a.y),
           h2 = __float2half_rn(a.z), h3 = __float2half_rn(a.w),
           h4 = __float2half_rn(c.x), h5 = __float2half_rn(c.y),
           h6 = __float2half_rn(c.z), h7 = __float2half_rn(c.w);
    __half l0 = __float2half_rn(a.x - __half2float(h0)),
           l1 = __float2half_rn(a.y - __half2float(h1)),
           l2 = __float2half_rn(a.z - __half2float(h2)),
           l3 = __float2half_rn(a.w - __half2float(h3)),
           l4 = __float2half_rn(c.x - __half2float(h4)),
           l5 = __float2half_rn(c.y - __half2float(h5)),
           l6 = __float2half_rn(c.z - __half2float(h6)),
           l7 = __float2half_rn(c.w - __half2float(h7));
    t1.x = (u32)__half_as_ushort(h0) | ((u32)__half_as_ushort(h1) << 16);
    t1.y = (u32)__half_as_ushort(h2) | ((u32)__half_as_ushort(h3) << 16);
    t1.z = (u32)__half_as_ushort(h4) | ((u32)__half_as_ushort(h5) << 16);
    t1.w = (u32)__half_as_ushort(h6) | ((u32)__half_as_ushort(h7) << 16);
    t2.x = (u32)__half_as_ushort(l0) | ((u32)__half_as_ushort(l1) << 16);
    t2.y = (u32)__half_as_ushort(l2) | ((u32)__half_as_ushort(l3) << 16);
    t2.z = (u32)__half_as_ushort(l4) | ((u32)__half_as_ushort(l5) << 16);
    t2.w = (u32)__half_as_ushort(l6) | ((u32)__half_as_ushort(l7) << 16);
}
} // namespace

extern __shared__ __align__(16) char smem1[];

__global__ __launch_bounds__(NT1, 3) void router_gemm_kernel(
    const float* __restrict__ z, const float* __restrict__ W)
{
    const int tid = threadIdx.x;
    const int wid = tid >> 5;
    const int lane = tid & 31;
    const int rb = blockIdx.x >> 3;       // row block (0..127)
    const int ks = blockIdx.x & 7;        // k eighth
    const int row0 = rb * BM;
    const int kbase = ks * KH;

    // ---- producer: thread owns 8 contiguous k of one z row + one W row ----
    const int pr = tid >> 2;              // 0..63
    const int pk = (tid & 3) * 8;         // 0,8,16,24
    const float* zg = z + (size_t)(row0 + pr) * D + kbase + pk;
    const float* wg = W + (size_t)pr * D + kbase + pk;
    const int sts = pr * ROWB + pk * 2;   // 16B-aligned (80 % 16 == 0)

    // ---- consumer: warp (mw 0..1, nw 0..3), tile m32 x n16 ----
    const int mw = wid & 1;
    const int nw = wid >> 1;
    const u32 sb = smem_u32(smem1);
    const u32 aB = sb + (u32)((mw * 32 + (lane & 15)) * ROWB + (lane >> 4) * 16);
    const u32 bB = sb + (u32)(B1_OFF + (nw * 16 + (lane & 7) + ((lane >> 4) << 3)) * ROWB
                              + (((lane >> 3) & 1) * 16));

    float acc[2][2][4];
#pragma unroll
    for (int i = 0; i < 2; ++i)
#pragma unroll
        for (int j = 0; j < 2; ++j)
#pragma unroll
            for (int q = 0; q < 4; ++q) acc[i][j][q] = 0.f;

    float4 vz0, vz1, vw0, vw1;

#define LDG_STAGE(t)                                        \
    do {                                                    \
        vz0 = *(const float4*)(zg + (t) * BK);              \
        vz1 = *(const float4*)(zg + (t) * BK + 4);          \
        vw0 = *(const float4*)(wg + (t) * BK);              \
        vw1 = *(const float4*)(wg + (t) * BK + 4);          \
    } while (0)

#define STS_STAGE(buf)                                      \
    do {                                                    \
        char* s_ = smem1 + (buf) * STG_B;                   \
        uint4 t1, t2;                                       \
        split8(vz0, vz1, t1, t2);                           \
        *(uint4*)(s_ + A1_OFF + sts) = t1;                  \
        *(uint4*)(s_ + A2_OFF + sts) = t2;                  \
        float4 w0 = make_float4(vw0.x * 64.f, vw0.y * 64.f, \
                                vw0.z * 64.f, vw0.w * 64.f);\
        float4 w1 = make_float4(vw1.x * 64.f, vw1.y * 64.f, \
                                vw1.z * 64.f, vw1.w * 64.f);\
        split8(w0, w1, t1, t2);                             \
        *(uint4*)(s_ + B1_OFF + sts) = t1;                  \
        *(uint4*)(s_ + B2_OFF + sts) = t2;                  \
    } while (0)

    LDG_STAGE(0);
    STS_STAGE(0);
    LDG_STAGE(1);
    STS_STAGE(1);
    LDG_STAGE(2);
    __syncthreads();

#pragma unroll
    for (int t = 0; t < NSTG; ++t) {
        const u32 so = (u32)((t % 3) * STG_B);
#pragma unroll
        for (int kc = 0; kc < 2; ++kc) {
            const u32 ko = kc * 32;  // 16 halfs
            u32 b1r[4], b2r[4];
            ldsm4(b1r, bB + so + ko);
            ldsm4(b2r, bB + so + ko + (B2_OFF - B1_OFF));
#pragma unroll
            for (int ms = 0; ms < 2; ++ms) {
                const u32 mo = (u32)(ms * 16 * ROWB);
                u32 a1r[4], a2r[4];
                ldsm4(a1r, aB + so + mo + ko);
                ldsm4(a2r, aB + so + mo + ko + A2_OFF);
                mma16(acc[ms][0], a1r, b1r[0], b1r[1]);
                mma16(acc[ms][0], a1r, b2r[0], b2r[1]);
                mma16(acc[ms][0], a2r, b1r[0], b1r[1]);
                mma16(acc[ms][1], a1r, b1r[2], b1r[3]);
                mma16(acc[ms][1], a1r, b2r[2], b2r[3]);
                mma16(acc[ms][1], a2r, b1r[2], b1r[3]);
            }
        }
        if (t + 2 < NSTG) STS_STAGE((t + 2) % 3);
        if (t + 3 < NSTG) LDG_STAGE(t + 3);
        __syncthreads();
    }

    // ---- write partial logits (scaled by 64) ----
    float* gp = g_part + (size_t)ks * NROWS * Kc;
    const int rr = lane >> 2;
    const int cc = (lane & 3) * 2;
#pragma unroll
    for (int ms = 0; ms < 2; ++ms) {
        const int row = row0 + mw * 32 + ms * 16 + rr;
#pragma unroll
        for (int nb = 0; nb < 2; ++nb) {
            const int col = nw * 16 + nb * 8 + cc;
            *(float2*)(gp + (size_t)row * Kc + col) =
                make_float2(acc[ms][nb][0], acc[ms][nb][1]);
            *(float2*)(gp + (size_t)(row + 8) * Kc + col) =
                make_float2(acc[ms][nb][2], acc[ms][nb][3]);
        }
    }
#undef LDG_STAGE
#undef STS_STAGE
}

// ---- K2: reduce partials + bias + top-k + softmax (warp per row) ----
__global__ __launch_bounds__(256, 8) void router_topk_kernel(
    const float* __restrict__ b, const int* __restrict__ kptr,
    float* __restrict__ out)
{
    const int wid = threadIdx.x >> 5;
    const int lane = threadIdx.x & 31;
    const int row = blockIdx.x * 8 + wid;
    const int c0 = lane * 2;

    float v0 = 0.f, v1 = 0.f;
#pragma unroll
    for (int ks = 0; ks < KSPLIT; ++ks) {
        const float2 p = *(const float2*)(
            g_part + (size_t)ks * NROWS * Kc + (size_t)row * Kc + c0);
        v0 += p.x;
        v1 += p.y;
    }
    v0 = v0 * 0.015625f + b[c0];
    v1 = v1 * 0.015625f + b[c0 + 1];

    int kk = kptr ? *kptr : 2;
    if (kk < 1) kk = 1;
    if (kk > Kc) kk = Kc;

    if (kk == 2) {
        // one-pass top-2 (val desc, idx asc — jax.lax.top_k tie-break)
        float hv, lv;
        int hi_, li_;
        if (v1 > v0) { hv = v1; hi_ = c0 + 1; lv = v0; li_ = c0; }
        else         { hv = v0; hi_ = c0;     lv = v1; li_ = c0 + 1; }
#pragma unroll
        for (int off = 16; off; off >>= 1) {
            const float ohv = __shfl_xor_sync(0xffffffffu, hv, off);
            const float olv = __shfl_xor_sync(0xffffffffu, lv, off);
            const int ohi = __shfl_xor_sync(0xffffffffu, hi_, off);
            const int oli = __shfl_xor_sync(0xffffffffu, li_, off);
            const bool w1_ = (hv > ohv) || (hv == ohv && hi_ < ohi);
            const float whv = w1_ ? hv : ohv;
            const int   whi = w1_ ? hi_ : ohi;
            const float lsv = w1_ ? ohv : hv;
            const int   lsi = w1_ ? ohi : hi_;
            const float wlv = w1_ ? lv : olv;
            const int   wli = w1_ ? li_ : oli;
            const bool sw = (lsv > wlv) || (lsv == wlv && lsi < wli);
            hv = whv; hi_ = whi;
            lv = sw ? lsv : wlv;
            li_ = sw ? lsi : wli;
        }
        const float elo = expf(lv - hv);
        const float inv = 1.0f / (1.0f + elo);
        const float eli = elo * inv;
        const float o0 = (c0 == hi_) ? inv : ((c0 == li_) ? eli : 0.f);
        const float o1 = (c0 + 1 == hi_) ? inv : ((c0 + 1 == li_) ? eli : 0.f);
        *(float2*)(out + (size_t)row * Kc + c0) = make_float2(o0, o1);
        return;
    }

    // generic k path
    unsigned sel = 0;
    float m = 0.f;
    for (int p = 0; p < kk; ++p) {
        float bv = (sel & 1) ? -3.4e38f : v0;
        int bi = c0;
        const float c1v = (sel & 2) ? -3.4e38f : v1;
        if (c1v > bv) { bv = c1v; bi = c0 + 1; }
#pragma unroll
        for (int off = 16; off; off >>= 1) {
            const float ov = __shfl_xor_sync(0xffffffffu, bv, off);
            const int oi = __shfl_xor_sync(0xffffffffu, bi, off);
            if (ov > bv || (ov == bv && oi < bi)) { bv = ov; bi = oi; }
        }
        if (p == 0) m = bv;
        if ((bi >> 1) == lane) sel |= 1u << (bi & 1);
    }
    const float e0 = (sel & 1) ? expf(v0 - m) : 0.f;
    const float e1 = (sel & 2) ? expf(v1 - m) : 0.f;
    float s = e0 + e1;
#pragma unroll
    for (int off = 16; off; off >>= 1) s += __shfl_xor_sync(0xffffffffu, s, off);
    const float inv = 1.0f / s;
    *(float2*)(out + (size_t)row * Kc + c0) = make_float2(e0 * inv, e1 * inv);
}

extern "C" void kernel_launch(void* const* d_in, const int* in_sizes, int n_in,
                              void* d_out, int out_size) {
    const float* z = (const float*)d_in[0];
    const float* W = (const float*)d_in[1];
    const float* b = (const float*)d_in[2];
    const int* kp = (n_in > 3) ? (const int*)d_in[3] : nullptr;
    float* out = (float*)d_out;

    cudaFuncSetAttribute(router_gemm_kernel,
                         cudaFuncAttributeMaxDynamicSharedMemorySize, SMEM1);

    const int N = in_sizes[0] / D;                      // 8192
    router_gemm_kernel<<<(N / BM) * KSPLIT, NT1, SMEM1>>>(z, W);
    router_topk_kernel<<<N / 8, 256>>>(b, kp, out);
    (void)out_size;
}